// round 1
// baseline (speedup 1.0000x reference)
#include <cuda_runtime.h>

// RBFN fused kernel: out = sqrt(1 + max(x2 + c2 - 2*X@C^T, 0)) @ W
// Shapes: xs[8192,128], centre[8192,128], weight[8192,64] -> out[8192,64], all fp32.

#define D_TOT   8192
#define N_TOT   8192
#define KD      128      // inner dim n
#define LD      64       // output cols l
#define BD      128      // d rows per block
#define BN      128      // N chunk per iteration
#define NSPLIT  2        // split N range across blocks -> 128 blocks
#define CHUNKS  (N_TOT / BN / NSPLIT)   // 32
#define THREADS 256
#define CPAD    132      // padded row stride for C / phi tile (float4-aligned, odd/4)

// Scratch for squared norms (device globals: no allocations allowed).
__device__ float x2_g[D_TOT];
__device__ float c2_g[N_TOT];

// ---------------------------------------------------------------------------
// Pass 1: row squared norms of xs and centre (both [8192,128]). One warp/row.
// ---------------------------------------------------------------------------
__global__ void sq_norms_kernel(const float* __restrict__ xs,
                                const float* __restrict__ centre) {
    int gw   = (blockIdx.x * blockDim.x + threadIdx.x) >> 5;
    int lane = threadIdx.x & 31;
    const float* src;
    float* dst;
    int row;
    if (gw < D_TOT) { src = xs;     dst = x2_g; row = gw; }
    else            { src = centre; dst = c2_g; row = gw - D_TOT; }

    float4 v = ((const float4*)(src + (size_t)row * KD))[lane];  // 32*4 = 128
    float s = v.x * v.x + v.y * v.y + v.z * v.z + v.w * v.w;
    #pragma unroll
    for (int off = 16; off; off >>= 1)
        s += __shfl_xor_sync(0xffffffffu, s, off);
    if (lane == 0) dst[row] = s;
}

// ---------------------------------------------------------------------------
// Pass 2: fused (X@C^T -> phi -> phi@W), tiled.
// Block b: d-tile = (b & 63), N-split = (b >> 6). 256 threads.
// GEMM1 micro-tile 8x8 per thread (16x16 thread grid over 128x128 S tile).
// GEMM2 micro-tile 8x4 per thread (16 ty x 16 tx over 128x64 acc tile).
// phi tile reuses the C smem buffer (C fully consumed before phi is written).
// ---------------------------------------------------------------------------
__global__ __launch_bounds__(THREADS, 1)
void rbfn_main_kernel(const float* __restrict__ xs,
                      const float* __restrict__ centre,
                      const float* __restrict__ weight,
                      float* __restrict__ out) {
    extern __shared__ float sm[];
    float* Xs    = sm;                    // [KD][BD]   K-major X tile (64 KB)
    float* CsPhi = Xs + KD * BD;          // [KD][CPAD] C K-major, then [BD][CPAD] phi
    float* Ws    = CsPhi + KD * CPAD;     // [BN][LD]   W chunk, row-major
    float* x2s   = Ws + BN * LD;          // [BD]
    float* c2s   = x2s + BD;              // [BN]

    const int tid = threadIdx.x;
    const int tx  = tid & 15;             // 0..15
    const int ty  = tid >> 4;             // 0..15
    const int db  = (blockIdx.x & 63) * BD;
    const int split = blockIdx.x >> 6;

    // ---- Load X tile once, transposed to K-major Xs[k][d]. ----
    // Lane mapping keeps global loads coalesced (4 rows x 128B per warp).
    #pragma unroll 1
    for (int it = 0; it < 16; ++it) {
        int d  = (tid >> 3) + ((it & 3) << 5);           // 0..127
        int kq = (tid & 7)  + ((it >> 2) << 3);          // 0..31 (float4 index)
        float4 v = ((const float4*)xs)[(size_t)(db + d) * (KD / 4) + kq];
        Xs[(4 * kq + 0) * BD + d] = v.x;
        Xs[(4 * kq + 1) * BD + d] = v.y;
        Xs[(4 * kq + 2) * BD + d] = v.z;
        Xs[(4 * kq + 3) * BD + d] = v.w;
    }
    if (tid < BD) x2s[tid] = x2_g[db + tid];

    float acc[8][4];
    #pragma unroll
    for (int i = 0; i < 8; ++i)
        #pragma unroll
        for (int j = 0; j < 4; ++j) acc[i][j] = 0.f;

    #pragma unroll 1
    for (int c = 0; c < CHUNKS; ++c) {
        const int nb = (split * CHUNKS + c) * BN;

        __syncthreads();  // previous GEMM2 done reading CsPhi/Ws; Xs ready on c==0

        // ---- Load C chunk transposed to K-major CsPhi[k][n]. ----
        #pragma unroll 1
        for (int it = 0; it < 16; ++it) {
            int n  = (tid >> 3) + ((it & 3) << 5);
            int kq = (tid & 7)  + ((it >> 2) << 3);
            float4 v = ((const float4*)centre)[(size_t)(nb + n) * (KD / 4) + kq];
            CsPhi[(4 * kq + 0) * CPAD + n] = v.x;
            CsPhi[(4 * kq + 1) * CPAD + n] = v.y;
            CsPhi[(4 * kq + 2) * CPAD + n] = v.z;
            CsPhi[(4 * kq + 3) * CPAD + n] = v.w;
        }
        // ---- Load W chunk (straight copy, row-major [n][l]). ----
        #pragma unroll 1
        for (int it = 0; it < 8; ++it) {
            int f  = it * THREADS + tid;
            int n  = f >> 4;
            int lq = f & 15;
            ((float4*)Ws)[n * (LD / 4) + lq] =
                ((const float4*)weight)[(size_t)(nb + n) * (LD / 4) + lq];
        }
        if (tid < BN) c2s[tid] = c2_g[nb + tid];
        __syncthreads();

        // ---- GEMM1: S[8][8] = X_tile @ C_chunk^T (outer-product over k). ----
        float S[8][8];
        #pragma unroll
        for (int i = 0; i < 8; ++i)
            #pragma unroll
            for (int j = 0; j < 8; ++j) S[i][j] = 0.f;

        #pragma unroll 2
        for (int k = 0; k < KD; ++k) {
            float4 a0 = *(const float4*)&Xs[k * BD + 8 * ty];
            float4 a1 = *(const float4*)&Xs[k * BD + 8 * ty + 4];
            float4 b0 = *(const float4*)&CsPhi[k * CPAD + 8 * tx];
            float4 b1 = *(const float4*)&CsPhi[k * CPAD + 8 * tx + 4];
            float a[8] = {a0.x, a0.y, a0.z, a0.w, a1.x, a1.y, a1.z, a1.w};
            float b[8] = {b0.x, b0.y, b0.z, b0.w, b1.x, b1.y, b1.z, b1.w};
            #pragma unroll
            for (int i = 0; i < 8; ++i)
                #pragma unroll
                for (int j = 0; j < 8; ++j)
                    S[i][j] = fmaf(a[i], b[j], S[i][j]);
        }

        __syncthreads();  // all GEMM1 reads of C done -> safe to overwrite with phi

        // ---- phi = sqrt(1 + max(x2 + c2 - 2S, 0)), stored [d][n] stride CPAD. ----
        float cc[8];
        #pragma unroll
        for (int j = 0; j < 8; ++j) cc[j] = c2s[8 * tx + j];
        #pragma unroll
        for (int i = 0; i < 8; ++i) {
            int d = 8 * ty + i;
            float xx = x2s[d];
            float p[8];
            #pragma unroll
            for (int j = 0; j < 8; ++j) {
                float r2 = fmaxf(xx + cc[j] - 2.f * S[i][j], 0.f);
                p[j] = sqrtf(1.f + r2);
            }
            *(float4*)&CsPhi[d * CPAD + 8 * tx]     = make_float4(p[0], p[1], p[2], p[3]);
            *(float4*)&CsPhi[d * CPAD + 8 * tx + 4] = make_float4(p[4], p[5], p[6], p[7]);
        }
        __syncthreads();

        // ---- GEMM2: acc[8][4] += phi[128x128] @ W[128x64] slice. ----
        #pragma unroll 2
        for (int k2 = 0; k2 < BN; ++k2) {
            float4 b = *(const float4*)&Ws[k2 * LD + 4 * tx];
            #pragma unroll
            for (int i = 0; i < 8; ++i) {
                float a = CsPhi[(8 * ty + i) * CPAD + k2];
                acc[i][0] = fmaf(a, b.x, acc[i][0]);
                acc[i][1] = fmaf(a, b.y, acc[i][1]);
                acc[i][2] = fmaf(a, b.z, acc[i][2]);
                acc[i][3] = fmaf(a, b.w, acc[i][3]);
            }
        }
    }

    // ---- Merge N-splits into out (out pre-zeroed by memset). ----
    #pragma unroll
    for (int i = 0; i < 8; ++i) {
        int d = db + 8 * ty + i;
        #pragma unroll
        for (int j = 0; j < 4; ++j)
            atomicAdd(&out[(size_t)d * LD + 4 * tx + j], acc[i][j]);
    }
}

// ---------------------------------------------------------------------------
extern "C" void kernel_launch(void* const* d_in, const int* in_sizes, int n_in,
                              void* d_out, int out_size) {
    const float* xs     = (const float*)d_in[0];
    const float* centre = (const float*)d_in[1];
    const float* weight = (const float*)d_in[2];
    float* out = (float*)d_out;

    const int smem_bytes = (KD * BD + KD * CPAD + BN * LD + BD + BN) * (int)sizeof(float);

    cudaFuncSetAttribute(rbfn_main_kernel,
                         cudaFuncAttributeMaxDynamicSharedMemorySize, smem_bytes);

    cudaMemsetAsync(d_out, 0, (size_t)out_size * sizeof(float));
    sq_norms_kernel<<<(2 * D_TOT) * 32 / THREADS, THREADS>>>(xs, centre);
    rbfn_main_kernel<<<64 * NSPLIT, THREADS, smem_bytes>>>(xs, centre, weight, out);
}

// round 3
// speedup vs baseline: 3.3002x; 3.3002x over previous
#include <cuda_runtime.h>
#include <cstdint>

// RBFN fused mma.sync(tf32) kernel (sm_80-era PTX; compiles for compute_103).
// out[8192,64] = sqrt(1 + max(x2 + c2 - 2*X@C^T, 0)) @ W

#define D_TOT   8192
#define N_TOT   8192
#define KD      128
#define LD      64
#define BD      128
#define BN      64
#define NSPLIT  2
#define CHUNKS  (N_TOT / BN / NSPLIT)   // 64
#define THREADS 256

// shared memory layout (32-bit word offsets)
#define XS_O 0                    // X tile  [128][132] tf32/raw fp32
#define CS_O 16896                // C chunk [64][132]
#define PH_O 25344                // phi hi  [128][68]
#define PL_O 34048                // phi lo  [128][68]
#define WS_O 42752                // W chunk [64 n][72 l] (RNA tf32)
#define X2_O 47360                // [128]
#define C2_O 47488                // [2][64] double-buffered
#define SM_WORDS 47616
#define SMEM_BYTES (SM_WORDS * 4)

__device__ float x2_g[D_TOT];
__device__ float c2_g[N_TOT];
__device__ float w_hi_g[N_TOT * LD];   // RNA-tf32-rounded weight

// ------------------------- helpers -------------------------
__device__ __forceinline__ uint32_t smem_u32(const void* p) {
    uint32_t a;
    asm("{ .reg .u64 t; cvta.to.shared.u64 t, %1; cvt.u32.u64 %0, t; }" : "=r"(a) : "l"(p));
    return a;
}
__device__ __forceinline__ float f2tf_rna(float x) {
    uint32_t r; asm("cvt.rna.tf32.f32 %0, %1;" : "=r"(r) : "f"(x));
    return __uint_as_float(r);
}
__device__ __forceinline__ float fsqrt_ap(float x) {
    float r; asm("sqrt.approx.f32 %0, %1;" : "=f"(r) : "f"(x)); return r;
}
__device__ __forceinline__ void cp16(uint32_t dst, const void* src) {
    asm volatile("cp.async.ca.shared.global [%0], [%1], 16;" :: "r"(dst), "l"(src) : "memory");
}
__device__ __forceinline__ void cpcommit() {
    asm volatile("cp.async.commit_group;" ::: "memory");
}
template <int N>
__device__ __forceinline__ void cpwait() {
    asm volatile("cp.async.wait_group %0;" :: "n"(N) : "memory");
}
__device__ __forceinline__ void mma_tf32(float* d, const uint32_t* a, const uint32_t* b) {
    asm volatile("mma.sync.aligned.m16n8k8.row.col.f32.tf32.tf32.f32 "
                 "{%0,%1,%2,%3}, {%4,%5,%6,%7}, {%8,%9}, {%0,%1,%2,%3};"
                 : "+f"(d[0]), "+f"(d[1]), "+f"(d[2]), "+f"(d[3])
                 : "r"(a[0]), "r"(a[1]), "r"(a[2]), "r"(a[3]),
                   "r"(b[0]), "r"(b[1]));
}

// ---------------------------------------------------------------------------
// Prologue A: row squared norms (exact fp32).
// ---------------------------------------------------------------------------
__global__ void sq_norms_kernel(const float* __restrict__ xs,
                                const float* __restrict__ centre) {
    int gw   = (blockIdx.x * blockDim.x + threadIdx.x) >> 5;
    int lane = threadIdx.x & 31;
    const float* src; float* dst; int row;
    if (gw < D_TOT) { src = xs;     dst = x2_g; row = gw; }
    else            { src = centre; dst = c2_g; row = gw - D_TOT; }
    float4 v = ((const float4*)(src + (size_t)row * KD))[lane];
    float s = v.x * v.x + v.y * v.y + v.z * v.z + v.w * v.w;
    #pragma unroll
    for (int off = 16; off; off >>= 1) s += __shfl_xor_sync(0xffffffffu, s, off);
    if (lane == 0) dst[row] = s;
}

// ---------------------------------------------------------------------------
// Prologue B: RNA-round weight to tf32 (removes truncation bias in GEMM2).
// ---------------------------------------------------------------------------
__global__ void wsplit_kernel(const float* __restrict__ weight) {
    int i = blockIdx.x * blockDim.x + threadIdx.x;
    w_hi_g[i] = f2tf_rna(weight[i]);
}

// ---------------------------------------------------------------------------
// Main fused kernel. 128 CTAs: d-tile = bid & 63, N-split = bid >> 6.
// 8 warps: wm = wid & 3 (32-row bands), wn = wid >> 2 (32-col bands).
// ---------------------------------------------------------------------------
__global__ __launch_bounds__(THREADS, 1)
void rbfn_main_kernel(const float* __restrict__ xs,
                      const float* __restrict__ centre,
                      float* __restrict__ out) {
    extern __shared__ float smf[];
    uint32_t* su = (uint32_t*)smf;
    const uint32_t sb = smem_u32(smf);

    const int tid = threadIdx.x;
    const int wid = tid >> 5, lid = tid & 31;
    const int gid = lid >> 2, ctg = lid & 3;
    const int wm = wid & 3, wn = wid >> 2;
    const int RM = wm * 32, CN = wn * 32;

    const int db    = (blockIdx.x & 63) * BD;
    const int split = blockIdx.x >> 6;

    // ---- issue X tile + x2 loads (group 0) ----
    #pragma unroll 1
    for (int it = 0; it < 16; ++it) {
        int idx = it * THREADS + tid;           // 4096 16B-chunks
        int row = idx >> 5, qc = idx & 31;
        cp16(sb + (XS_O + row * 132 + qc * 4) * 4,
             xs + (size_t)(db + row) * KD + qc * 4);
    }
    if (tid < 32) cp16(sb + (X2_O + tid * 4) * 4, x2_g + db + tid * 4);
    cpcommit();

    // ---- issue C chunk 0 + c2 (group 1) ----
    {
        const int nb0 = split * CHUNKS * BN;
        #pragma unroll 1
        for (int it = 0; it < 8; ++it) {
            int idx = it * THREADS + tid;       // 2048 chunks
            int row = idx >> 5, qc = idx & 31;
            cp16(sb + (CS_O + row * 132 + qc * 4) * 4,
                 centre + (size_t)(nb0 + row) * KD + qc * 4);
        }
        if (tid < 16) cp16(sb + (C2_O + tid * 4) * 4, c2_g + nb0 + tid * 4);
        cpcommit();
    }

    float O[2][4][4];
    #pragma unroll
    for (int mt = 0; mt < 2; ++mt)
        #pragma unroll
        for (int nt = 0; nt < 4; ++nt)
            #pragma unroll
            for (int r = 0; r < 4; ++r) O[mt][nt][r] = 0.f;

    #pragma unroll 1
    for (int c = 0; c < CHUNKS; ++c) {
        const int nb  = (split * CHUNKS + c) * BN;
        const int par = c & 1;

        // ---- issue W chunk c (buffer free: sync at end of prev iter) ----
        #pragma unroll 1
        for (int it = 0; it < 4; ++it) {
            int idx = it * THREADS + tid;       // 1024 chunks
            int row = idx >> 4, qc = idx & 15;
            cp16(sb + (WS_O + row * 72 + qc * 4) * 4,
                 w_hi_g + (size_t)(nb + row) * LD + qc * 4);
        }
        cpcommit();

        cpwait<1>();          // X (c==0) and C_c complete; W_c may be pending
        __syncthreads();

        // ---- GEMM1: S = X @ C^T ----
        float S[2][4][4];
        #pragma unroll
        for (int mt = 0; mt < 2; ++mt)
            #pragma unroll
            for (int nt = 0; nt < 4; ++nt)
                #pragma unroll
                for (int r = 0; r < 4; ++r) S[mt][nt][r] = 0.f;

        #pragma unroll
        for (int k0 = 0; k0 < KD; k0 += 8) {
            uint32_t a[2][4], b[4][2];
            #pragma unroll
            for (int mt = 0; mt < 2; ++mt) {
                int r = RM + mt * 16 + gid;
                a[mt][0] = su[XS_O + r * 132 + k0 + ctg];
                a[mt][1] = su[XS_O + (r + 8) * 132 + k0 + ctg];
                a[mt][2] = su[XS_O + r * 132 + k0 + ctg + 4];
                a[mt][3] = su[XS_O + (r + 8) * 132 + k0 + ctg + 4];
            }
            #pragma unroll
            for (int nt = 0; nt < 4; ++nt) {
                int n = CN + nt * 8 + gid;
                b[nt][0] = su[CS_O + n * 132 + k0 + ctg];
                b[nt][1] = su[CS_O + n * 132 + k0 + ctg + 4];
            }
            #pragma unroll
            for (int mt = 0; mt < 2; ++mt)
                #pragma unroll
                for (int nt = 0; nt < 4; ++nt)
                    mma_tf32(S[mt][nt], a[mt], b[nt]);
        }

        __syncthreads();      // all warps finished reading C_c

        // ---- prefetch C_{c+1} + c2 into freed buffer ----
        if (c + 1 < CHUNKS) {
            const int nbn = nb + BN;
            #pragma unroll 1
            for (int it = 0; it < 8; ++it) {
                int idx = it * THREADS + tid;
                int row = idx >> 5, qc = idx & 31;
                cp16(sb + (CS_O + row * 132 + qc * 4) * 4,
                     centre + (size_t)(nbn + row) * KD + qc * 4);
            }
            if (tid < 16)
                cp16(sb + (C2_O + (par ^ 1) * 64 + tid * 4) * 4, c2_g + nbn + tid * 4);
            cpcommit();
            cpwait<1>();      // W_c complete
        } else {
            cpwait<0>();
        }

        // ---- epilogue: phi = sqrt(1 + max(x2+c2-2S,0)), split hi/lo ----
        #pragma unroll
        for (int mt = 0; mt < 2; ++mt) {
            int rA = RM + mt * 16 + gid, rB = rA + 8;
            float xA = smf[X2_O + rA], xB = smf[X2_O + rB];
            #pragma unroll
            for (int nt = 0; nt < 4; ++nt) {
                int c0 = CN + nt * 8 + 2 * ctg;
                float cc0 = smf[C2_O + par * 64 + c0];
                float cc1 = smf[C2_O + par * 64 + c0 + 1];
                float p0 = fsqrt_ap(1.f + fmaxf(fmaf(-2.f, S[mt][nt][0], xA + cc0), 0.f));
                float p1 = fsqrt_ap(1.f + fmaxf(fmaf(-2.f, S[mt][nt][1], xA + cc1), 0.f));
                float p2 = fsqrt_ap(1.f + fmaxf(fmaf(-2.f, S[mt][nt][2], xB + cc0), 0.f));
                float p3 = fsqrt_ap(1.f + fmaxf(fmaf(-2.f, S[mt][nt][3], xB + cc1), 0.f));
                float h0 = f2tf_rna(p0), h1 = f2tf_rna(p1);
                float h2 = f2tf_rna(p2), h3 = f2tf_rna(p3);
                *(uint2*)&su[PH_O + rA * 68 + c0] =
                    make_uint2(__float_as_uint(h0), __float_as_uint(h1));
                *(uint2*)&su[PH_O + rB * 68 + c0] =
                    make_uint2(__float_as_uint(h2), __float_as_uint(h3));
                *(uint2*)&su[PL_O + rA * 68 + c0] =
                    make_uint2(__float_as_uint(p0 - h0), __float_as_uint(p1 - h1));
                *(uint2*)&su[PL_O + rB * 68 + c0] =
                    make_uint2(__float_as_uint(p2 - h2), __float_as_uint(p3 - h3));
            }
        }
        __syncthreads();      // phi visible; W_c ready for everyone

        // ---- GEMM2: O += phi_hi @ W + phi_lo @ W ----
        #pragma unroll
        for (int k0 = 0; k0 < BN; k0 += 8) {
            uint32_t ah[2][4], al[2][4], bw[4][2];
            #pragma unroll
            for (int mt = 0; mt < 2; ++mt) {
                int r = RM + mt * 16 + gid;
                ah[mt][0] = su[PH_O + r * 68 + k0 + ctg];
                ah[mt][1] = su[PH_O + (r + 8) * 68 + k0 + ctg];
                ah[mt][2] = su[PH_O + r * 68 + k0 + ctg + 4];
                ah[mt][3] = su[PH_O + (r + 8) * 68 + k0 + ctg + 4];
                al[mt][0] = su[PL_O + r * 68 + k0 + ctg];
                al[mt][1] = su[PL_O + (r + 8) * 68 + k0 + ctg];
                al[mt][2] = su[PL_O + r * 68 + k0 + ctg + 4];
                al[mt][3] = su[PL_O + (r + 8) * 68 + k0 + ctg + 4];
            }
            #pragma unroll
            for (int nt = 0; nt < 4; ++nt) {
                int cl = CN + nt * 8 + gid;
                bw[nt][0] = su[WS_O + (k0 + ctg) * 72 + cl];
                bw[nt][1] = su[WS_O + (k0 + ctg + 4) * 72 + cl];
            }
            #pragma unroll
            for (int mt = 0; mt < 2; ++mt)
                #pragma unroll
                for (int nt = 0; nt < 4; ++nt) {
                    mma_tf32(O[mt][nt], ah[mt], bw[nt]);
                    mma_tf32(O[mt][nt], al[mt], bw[nt]);
                }
        }
        __syncthreads();      // W_c / phi free for next chunk
    }

    // ---- merge N-splits ----
    #pragma unroll
    for (int mt = 0; mt < 2; ++mt) {
        int rA = db + RM + mt * 16 + gid;
        #pragma unroll
        for (int nt = 0; nt < 4; ++nt) {
            int c0 = CN + nt * 8 + 2 * ctg;
            atomicAdd(&out[(size_t)rA * LD + c0],           O[mt][nt][0]);
            atomicAdd(&out[(size_t)rA * LD + c0 + 1],       O[mt][nt][1]);
            atomicAdd(&out[(size_t)(rA + 8) * LD + c0],     O[mt][nt][2]);
            atomicAdd(&out[(size_t)(rA + 8) * LD + c0 + 1], O[mt][nt][3]);
        }
    }
}

// ---------------------------------------------------------------------------
extern "C" void kernel_launch(void* const* d_in, const int* in_sizes, int n_in,
                              void* d_out, int out_size) {
    const float* xs     = (const float*)d_in[0];
    const float* centre = (const float*)d_in[1];
    const float* weight = (const float*)d_in[2];
    float* out = (float*)d_out;

    cudaFuncSetAttribute(rbfn_main_kernel,
                         cudaFuncAttributeMaxDynamicSharedMemorySize, SMEM_BYTES);

    cudaMemsetAsync(d_out, 0, (size_t)out_size * sizeof(float));
    sq_norms_kernel<<<(2 * D_TOT) * 32 / THREADS, THREADS>>>(xs, centre);
    wsplit_kernel<<<(N_TOT * LD) / THREADS, THREADS>>>(weight);
    rbfn_main_kernel<<<64 * NSPLIT, THREADS, SMEM_BYTES>>>(xs, centre, out);
}

// round 4
// speedup vs baseline: 4.9846x; 1.5104x over previous
#include <cuda_runtime.h>
#include <cuda_fp16.h>
#include <cstdint>

// RBFN fused kernel: GEMM1 in fp16 mma.sync (m16n8k16), GEMM2 in tf32 (m16n8k8).
// out[8192,64] = sqrt(1 + max(x2 + c2 - 2*X@C^T, 0)) @ W

#define D_TOT   8192
#define N_TOT   8192
#define KD      128
#define LD      64
#define BD      128
#define BN      64
#define NSPLIT  2
#define CHUNKS  (N_TOT / BN / NSPLIT)   // 64
#define THREADS 256

// shared memory layout (32-bit word offsets)
#define XH_O 0                    // X tile  [128 rows][68 words] (half2-packed, 64 data + 4 pad)
#define CH_O 8704                 // C chunk [64][68] half2
#define PH_O 13056                // phi (rna-tf32) [128][68] fp32 words, 64 data + 4 pad
#define WS_O 21760                // W chunk [64 k][72 l] fp32 (rna tf32)
#define X2_O 26368                // [128]
#define C2_O 26496                // [2][64] double-buffered
#define SM_WORDS 26624
#define SMEM_BYTES (SM_WORDS * 4)

__device__ float  x2_g[D_TOT];
__device__ float  c2_g[N_TOT];
__device__ __half xh_g[D_TOT * KD];    // fp16-rn xs
__device__ __half ch_g[N_TOT * KD];    // fp16-rn centre
__device__ float  w_hi_g[N_TOT * LD];  // RNA-tf32 weight

// ------------------------- helpers -------------------------
__device__ __forceinline__ uint32_t smem_u32(const void* p) {
    uint32_t a;
    asm("{ .reg .u64 t; cvta.to.shared.u64 t, %1; cvt.u32.u64 %0, t; }" : "=r"(a) : "l"(p));
    return a;
}
__device__ __forceinline__ float f2tf_rna(float x) {
    uint32_t r; asm("cvt.rna.tf32.f32 %0, %1;" : "=r"(r) : "f"(x));
    return __uint_as_float(r);
}
__device__ __forceinline__ float fsqrt_ap(float x) {
    float r; asm("sqrt.approx.f32 %0, %1;" : "=f"(r) : "f"(x)); return r;
}
__device__ __forceinline__ void cp16(uint32_t dst, const void* src) {
    asm volatile("cp.async.ca.shared.global [%0], [%1], 16;" :: "r"(dst), "l"(src) : "memory");
}
__device__ __forceinline__ void cpcommit() {
    asm volatile("cp.async.commit_group;" ::: "memory");
}
template <int N>
__device__ __forceinline__ void cpwait() {
    asm volatile("cp.async.wait_group %0;" :: "n"(N) : "memory");
}
// tf32 m16n8k8
__device__ __forceinline__ void mma_tf32(float* d, const uint32_t* a, const uint32_t* b) {
    asm volatile("mma.sync.aligned.m16n8k8.row.col.f32.tf32.tf32.f32 "
                 "{%0,%1,%2,%3}, {%4,%5,%6,%7}, {%8,%9}, {%0,%1,%2,%3};"
                 : "+f"(d[0]), "+f"(d[1]), "+f"(d[2]), "+f"(d[3])
                 : "r"(a[0]), "r"(a[1]), "r"(a[2]), "r"(a[3]),
                   "r"(b[0]), "r"(b[1]));
}
// fp16 m16n8k16, fp32 accumulate
__device__ __forceinline__ void mma_f16(float* d, const uint32_t* a, const uint32_t* b) {
    asm volatile("mma.sync.aligned.m16n8k16.row.col.f32.f16.f16.f32 "
                 "{%0,%1,%2,%3}, {%4,%5,%6,%7}, {%8,%9}, {%0,%1,%2,%3};"
                 : "+f"(d[0]), "+f"(d[1]), "+f"(d[2]), "+f"(d[3])
                 : "r"(a[0]), "r"(a[1]), "r"(a[2]), "r"(a[3]),
                   "r"(b[0]), "r"(b[1]));
}

// ---------------------------------------------------------------------------
// Prologue A: row squared norms (exact fp32) + fp16-rn conversion of rows.
// One warp per row; 2*8192 rows total.
// ---------------------------------------------------------------------------
__global__ void norms_half_kernel(const float* __restrict__ xs,
                                  const float* __restrict__ centre) {
    int gw   = (blockIdx.x * blockDim.x + threadIdx.x) >> 5;
    int lane = threadIdx.x & 31;
    const float* src; float* dst; __half* dsth; int row;
    if (gw < D_TOT) { src = xs;     dst = x2_g; dsth = xh_g; row = gw; }
    else            { src = centre; dst = c2_g; dsth = ch_g; row = gw - D_TOT; }
    float4 v = ((const float4*)(src + (size_t)row * KD))[lane];

    __half2 h01 = __float22half2_rn(make_float2(v.x, v.y));
    __half2 h23 = __float22half2_rn(make_float2(v.z, v.w));
    uint2 u = make_uint2(*(uint32_t*)&h01, *(uint32_t*)&h23);
    *(uint2*)(dsth + (size_t)row * KD + 4 * lane) = u;

    float s = v.x * v.x + v.y * v.y + v.z * v.z + v.w * v.w;
    #pragma unroll
    for (int off = 16; off; off >>= 1) s += __shfl_xor_sync(0xffffffffu, s, off);
    if (lane == 0) dst[row] = s;
}

// ---------------------------------------------------------------------------
// Prologue B: RNA-round weight to tf32.
// ---------------------------------------------------------------------------
__global__ void wsplit_kernel(const float* __restrict__ weight) {
    int i = blockIdx.x * blockDim.x + threadIdx.x;
    w_hi_g[i] = f2tf_rna(weight[i]);
}

// ---------------------------------------------------------------------------
// Main fused kernel. 128 CTAs: d-tile = bid & 63, N-split = bid >> 6.
// 8 warps: wm = wid & 3 (32-row bands), wn = wid >> 2 (32-col bands).
// ---------------------------------------------------------------------------
__global__ __launch_bounds__(THREADS, 1)
void rbfn_main_kernel(float* __restrict__ out) {
    extern __shared__ float smf[];
    uint32_t* su = (uint32_t*)smf;
    const uint32_t sb = smem_u32(smf);

    const int tid = threadIdx.x;
    const int wid = tid >> 5, lid = tid & 31;
    const int gid = lid >> 2, ctg = lid & 3;
    const int wm = wid & 3, wn = wid >> 2;
    const int RM = wm * 32, CN = wn * 32;

    const int db    = (blockIdx.x & 63) * BD;
    const int split = blockIdx.x >> 6;

    // ---- issue X tile (fp16) + x2 loads (group 0) ----
    // 128 rows x 128 halves = 2048 16B chunks.
    #pragma unroll 1
    for (int it = 0; it < 8; ++it) {
        int idx = it * THREADS + tid;
        int row = idx >> 4, qc = idx & 15;
        cp16(sb + (XH_O + row * 68 + qc * 4) * 4,
             xh_g + (size_t)(db + row) * KD + qc * 8);
    }
    if (tid < 32) cp16(sb + (X2_O + tid * 4) * 4, x2_g + db + tid * 4);
    cpcommit();

    // ---- issue C chunk 0 (fp16) + c2 (group 1) ----
    {
        const int nb0 = split * CHUNKS * BN;
        #pragma unroll 1
        for (int it = 0; it < 4; ++it) {
            int idx = it * THREADS + tid;        // 1024 chunks
            int row = idx >> 4, qc = idx & 15;
            cp16(sb + (CH_O + row * 68 + qc * 4) * 4,
                 ch_g + (size_t)(nb0 + row) * KD + qc * 8);
        }
        if (tid < 16) cp16(sb + (C2_O + tid * 4) * 4, c2_g + nb0 + tid * 4);
        cpcommit();
    }

    float O[2][4][4];
    #pragma unroll
    for (int mt = 0; mt < 2; ++mt)
        #pragma unroll
        for (int nt = 0; nt < 4; ++nt)
            #pragma unroll
            for (int r = 0; r < 4; ++r) O[mt][nt][r] = 0.f;

    #pragma unroll 1
    for (int c = 0; c < CHUNKS; ++c) {
        const int nb  = (split * CHUNKS + c) * BN;
        const int par = c & 1;

        // ---- issue W chunk c ----
        #pragma unroll 1
        for (int it = 0; it < 4; ++it) {
            int idx = it * THREADS + tid;        // 1024 chunks
            int row = idx >> 4, qc = idx & 15;
            cp16(sb + (WS_O + row * 72 + qc * 4) * 4,
                 w_hi_g + (size_t)(nb + row) * LD + qc * 4);
        }
        cpcommit();

        cpwait<1>();          // X (c==0) and C_c complete; W_c may be pending
        __syncthreads();

        // ---- GEMM1 (fp16): S = X @ C^T ----
        float S[2][4][4];
        #pragma unroll
        for (int mt = 0; mt < 2; ++mt)
            #pragma unroll
            for (int nt = 0; nt < 4; ++nt)
                #pragma unroll
                for (int r = 0; r < 4; ++r) S[mt][nt][r] = 0.f;

        #pragma unroll
        for (int kw = 0; kw < 64; kw += 8) {     // word index over k (16 halves/step)
            uint32_t a[2][4], b[4][2];
            #pragma unroll
            for (int mt = 0; mt < 2; ++mt) {
                int r = RM + mt * 16 + gid;
                a[mt][0] = su[XH_O + r * 68 + kw + ctg];
                a[mt][1] = su[XH_O + (r + 8) * 68 + kw + ctg];
                a[mt][2] = su[XH_O + r * 68 + kw + ctg + 4];
                a[mt][3] = su[XH_O + (r + 8) * 68 + kw + ctg + 4];
            }
            #pragma unroll
            for (int nt = 0; nt < 4; ++nt) {
                int n = CN + nt * 8 + gid;
                b[nt][0] = su[CH_O + n * 68 + kw + ctg];
                b[nt][1] = su[CH_O + n * 68 + kw + ctg + 4];
            }
            #pragma unroll
            for (int mt = 0; mt < 2; ++mt)
                #pragma unroll
                for (int nt = 0; nt < 4; ++nt)
                    mma_f16(S[mt][nt], a[mt], b[nt]);
        }

        __syncthreads();      // all warps finished reading C_c

        // ---- prefetch C_{c+1} + c2 into freed buffer ----
        if (c + 1 < CHUNKS) {
            const int nbn = nb + BN;
            #pragma unroll 1
            for (int it = 0; it < 4; ++it) {
                int idx = it * THREADS + tid;
                int row = idx >> 4, qc = idx & 15;
                cp16(sb + (CH_O + row * 68 + qc * 4) * 4,
                     ch_g + (size_t)(nbn + row) * KD + qc * 8);
            }
            if (tid < 16)
                cp16(sb + (C2_O + (par ^ 1) * 64 + tid * 4) * 4, c2_g + nbn + tid * 4);
            cpcommit();
            cpwait<1>();      // W_c complete
        } else {
            cpwait<0>();
        }

        // ---- epilogue: phi = sqrt(1 + max(x2+c2-2S,0)) -> rna tf32 ----
        #pragma unroll
        for (int mt = 0; mt < 2; ++mt) {
            int rA = RM + mt * 16 + gid, rB = rA + 8;
            float xA = smf[X2_O + rA], xB = smf[X2_O + rB];
            #pragma unroll
            for (int nt = 0; nt < 4; ++nt) {
                int c0 = CN + nt * 8 + 2 * ctg;
                float cc0 = smf[C2_O + par * 64 + c0];
                float cc1 = smf[C2_O + par * 64 + c0 + 1];
                float p0 = fsqrt_ap(1.f + fmaxf(fmaf(-2.f, S[mt][nt][0], xA + cc0), 0.f));
                float p1 = fsqrt_ap(1.f + fmaxf(fmaf(-2.f, S[mt][nt][1], xA + cc1), 0.f));
                float p2 = fsqrt_ap(1.f + fmaxf(fmaf(-2.f, S[mt][nt][2], xB + cc0), 0.f));
                float p3 = fsqrt_ap(1.f + fmaxf(fmaf(-2.f, S[mt][nt][3], xB + cc1), 0.f));
                float h0 = f2tf_rna(p0), h1 = f2tf_rna(p1);
                float h2 = f2tf_rna(p2), h3 = f2tf_rna(p3);
                *(uint2*)&su[PH_O + rA * 68 + c0] =
                    make_uint2(__float_as_uint(h0), __float_as_uint(h1));
                *(uint2*)&su[PH_O + rB * 68 + c0] =
                    make_uint2(__float_as_uint(h2), __float_as_uint(h3));
            }
        }
        __syncthreads();      // phi visible; W_c ready for everyone

        // ---- GEMM2 (tf32): O += phi @ W ----
        #pragma unroll
        for (int k0 = 0; k0 < BN; k0 += 8) {
            uint32_t ah[2][4], bw[4][2];
            #pragma unroll
            for (int mt = 0; mt < 2; ++mt) {
                int r = RM + mt * 16 + gid;
                ah[mt][0] = su[PH_O + r * 68 + k0 + ctg];
                ah[mt][1] = su[PH_O + (r + 8) * 68 + k0 + ctg];
                ah[mt][2] = su[PH_O + r * 68 + k0 + ctg + 4];
                ah[mt][3] = su[PH_O + (r + 8) * 68 + k0 + ctg + 4];
            }
            #pragma unroll
            for (int nt = 0; nt < 4; ++nt) {
                int cl = CN + nt * 8 + gid;
                bw[nt][0] = su[WS_O + (k0 + ctg) * 72 + cl];
                bw[nt][1] = su[WS_O + (k0 + ctg + 4) * 72 + cl];
            }
            #pragma unroll
            for (int mt = 0; mt < 2; ++mt)
                #pragma unroll
                for (int nt = 0; nt < 4; ++nt)
                    mma_tf32(O[mt][nt], ah[mt], bw[nt]);
        }
        __syncthreads();      // W_c / phi free for next chunk
    }

    // ---- merge N-splits ----
    #pragma unroll
    for (int mt = 0; mt < 2; ++mt) {
        int rA = db + RM + mt * 16 + gid;
        #pragma unroll
        for (int nt = 0; nt < 4; ++nt) {
            int c0 = CN + nt * 8 + 2 * ctg;
            atomicAdd(&out[(size_t)rA * LD + c0],           O[mt][nt][0]);
            atomicAdd(&out[(size_t)rA * LD + c0 + 1],       O[mt][nt][1]);
            atomicAdd(&out[(size_t)(rA + 8) * LD + c0],     O[mt][nt][2]);
            atomicAdd(&out[(size_t)(rA + 8) * LD + c0 + 1], O[mt][nt][3]);
        }
    }
}

// ---------------------------------------------------------------------------
extern "C" void kernel_launch(void* const* d_in, const int* in_sizes, int n_in,
                              void* d_out, int out_size) {
    const float* xs     = (const float*)d_in[0];
    const float* centre = (const float*)d_in[1];
    const float* weight = (const float*)d_in[2];
    float* out = (float*)d_out;

    cudaFuncSetAttribute(rbfn_main_kernel,
                         cudaFuncAttributeMaxDynamicSharedMemorySize, SMEM_BYTES);

    cudaMemsetAsync(d_out, 0, (size_t)out_size * sizeof(float));
    norms_half_kernel<<<(2 * D_TOT) * 32 / THREADS, THREADS>>>(xs, centre);
    wsplit_kernel<<<(N_TOT * LD) / THREADS, THREADS>>>(weight);
    rbfn_main_kernel<<<64 * NSPLIT, THREADS, SMEM_BYTES>>>(out);
}

// round 5
// speedup vs baseline: 6.0289x; 1.2095x over previous
#include <cuda_runtime.h>
#include <cuda_fp16.h>
#include <cstdint>

// RBFN fused kernel: GEMM1 fp16 mma.sync m16n8k16, GEMM2 fp16 m16n8k16 (f32 acc).
// out[8192,64] = sqrt(1 + max(x2 + c2 - 2*X@C^T, 0)) @ W

#define D_TOT   8192
#define N_TOT   8192
#define KD      128
#define LD      64
#define BD      128
#define BN      64
#define NSPLIT  2
#define CHUNKS  (N_TOT / BN / NSPLIT)   // 64
#define THREADS 256

// shared memory layout (32-bit word offsets)
#define XH_O 0                    // X tile  [128 rows][68 words] half2 (64 data + 4 pad)
#define CH_O 8704                 // C chunk [64][68] half2
#define PH_O 13056                // phi fp16 [128 rows][36 words] (32 data + 4 pad)
#define WS_O 17664                // W^T fp16 [64 l][36 words]
#define X2_O 19968                // [128]
#define C2_O 20096                // [2][64] double-buffered
#define SM_WORDS 20224
#define SMEM_BYTES (SM_WORDS * 4)

__device__ float  x2_g[D_TOT];
__device__ float  c2_g[N_TOT];
__device__ __half xh_g[D_TOT * KD];    // fp16-rn xs
__device__ __half ch_g[N_TOT * KD];    // fp16-rn centre
__device__ __half wt_g[LD * N_TOT];    // fp16-rn weight, TRANSPOSED [l][n]

// ------------------------- helpers -------------------------
__device__ __forceinline__ uint32_t smem_u32(const void* p) {
    uint32_t a;
    asm("{ .reg .u64 t; cvta.to.shared.u64 t, %1; cvt.u32.u64 %0, t; }" : "=r"(a) : "l"(p));
    return a;
}
__device__ __forceinline__ float fsqrt_ap(float x) {
    float r; asm("sqrt.approx.f32 %0, %1;" : "=f"(r) : "f"(x)); return r;
}
__device__ __forceinline__ void cp16(uint32_t dst, const void* src) {
    asm volatile("cp.async.ca.shared.global [%0], [%1], 16;" :: "r"(dst), "l"(src) : "memory");
}
__device__ __forceinline__ void cpcommit() {
    asm volatile("cp.async.commit_group;" ::: "memory");
}
template <int N>
__device__ __forceinline__ void cpwait() {
    asm volatile("cp.async.wait_group %0;" :: "n"(N) : "memory");
}
// fp16 m16n8k16, fp32 accumulate
__device__ __forceinline__ void mma_f16(float* d, const uint32_t* a, const uint32_t* b) {
    asm volatile("mma.sync.aligned.m16n8k16.row.col.f32.f16.f16.f32 "
                 "{%0,%1,%2,%3}, {%4,%5,%6,%7}, {%8,%9}, {%0,%1,%2,%3};"
                 : "+f"(d[0]), "+f"(d[1]), "+f"(d[2]), "+f"(d[3])
                 : "r"(a[0]), "r"(a[1]), "r"(a[2]), "r"(a[3]),
                   "r"(b[0]), "r"(b[1]));
}

// ---------------------------------------------------------------------------
// Prologue A: row squared norms (exact fp32) + fp16-rn rows of xs/centre.
// ---------------------------------------------------------------------------
__global__ void norms_half_kernel(const float* __restrict__ xs,
                                  const float* __restrict__ centre) {
    int gw   = (blockIdx.x * blockDim.x + threadIdx.x) >> 5;
    int lane = threadIdx.x & 31;
    const float* src; float* dst; __half* dsth; int row;
    if (gw < D_TOT) { src = xs;     dst = x2_g; dsth = xh_g; row = gw; }
    else            { src = centre; dst = c2_g; dsth = ch_g; row = gw - D_TOT; }
    float4 v = ((const float4*)(src + (size_t)row * KD))[lane];

    __half2 h01 = __float22half2_rn(make_float2(v.x, v.y));
    __half2 h23 = __float22half2_rn(make_float2(v.z, v.w));
    uint2 u = make_uint2(*(uint32_t*)&h01, *(uint32_t*)&h23);
    *(uint2*)(dsth + (size_t)row * KD + 4 * lane) = u;

    float s = v.x * v.x + v.y * v.y + v.z * v.z + v.w * v.w;
    #pragma unroll
    for (int off = 16; off; off >>= 1) s += __shfl_xor_sync(0xffffffffu, s, off);
    if (lane == 0) dst[row] = s;
}

// ---------------------------------------------------------------------------
// Prologue B: transpose weight [N][L] -> fp16 [L][N].
// ---------------------------------------------------------------------------
__global__ void wtrans_kernel(const float* __restrict__ weight) {
    int idx = blockIdx.x * blockDim.x + threadIdx.x;   // over LD*N_TOT
    int l = idx >> 13;                                 // /8192
    int n = idx & 8191;
    wt_g[(size_t)l * N_TOT + n] = __float2half_rn(weight[(size_t)n * LD + l]);
}

// ---------------------------------------------------------------------------
// Main fused kernel. 128 CTAs: d-tile = bid & 63, N-split = bid >> 6.
// 8 warps: wm = wid & 3 (32-row bands), wn = wid >> 2 (32-col bands).
// ---------------------------------------------------------------------------
__global__ __launch_bounds__(THREADS, 1)
void rbfn_main_kernel(float* __restrict__ out) {
    extern __shared__ float smf[];
    uint32_t* su = (uint32_t*)smf;
    const uint32_t sb = smem_u32(smf);

    const int tid = threadIdx.x;
    const int wid = tid >> 5, lid = tid & 31;
    const int gid = lid >> 2, ctg = lid & 3;
    const int wm = wid & 3, wn = wid >> 2;
    const int RM = wm * 32, CN = wn * 32;

    const int db    = (blockIdx.x & 63) * BD;
    const int split = blockIdx.x >> 6;

    // ---- issue X tile (fp16) + x2 loads (group 0) ----
    #pragma unroll 1
    for (int it = 0; it < 8; ++it) {
        int idx = it * THREADS + tid;          // 2048 16B chunks
        int row = idx >> 4, qc = idx & 15;
        cp16(sb + (XH_O + row * 68 + qc * 4) * 4,
             xh_g + (size_t)(db + row) * KD + qc * 8);
    }
    if (tid < 32) cp16(sb + (X2_O + tid * 4) * 4, x2_g + db + tid * 4);
    cpcommit();

    // ---- issue C chunk 0 (fp16) + c2 (group 1) ----
    {
        const int nb0 = split * CHUNKS * BN;
        #pragma unroll 1
        for (int it = 0; it < 4; ++it) {
            int idx = it * THREADS + tid;      // 1024 chunks
            int row = idx >> 4, qc = idx & 15;
            cp16(sb + (CH_O + row * 68 + qc * 4) * 4,
                 ch_g + (size_t)(nb0 + row) * KD + qc * 8);
        }
        if (tid < 16) cp16(sb + (C2_O + tid * 4) * 4, c2_g + nb0 + tid * 4);
        cpcommit();
    }

    float O[2][4][4];
    #pragma unroll
    for (int mt = 0; mt < 2; ++mt)
        #pragma unroll
        for (int nt = 0; nt < 4; ++nt)
            #pragma unroll
            for (int r = 0; r < 4; ++r) O[mt][nt][r] = 0.f;

    #pragma unroll 1
    for (int c = 0; c < CHUNKS; ++c) {
        const int nb  = (split * CHUNKS + c) * BN;
        const int par = c & 1;

        // ---- issue W^T chunk c: 64 l-rows x 64 halves (128B each) ----
        #pragma unroll 1
        for (int it = 0; it < 2; ++it) {
            int idx = it * THREADS + tid;      // 512 chunks
            int l = idx >> 3, qc = idx & 7;
            cp16(sb + (WS_O + l * 36 + qc * 4) * 4,
                 wt_g + (size_t)l * N_TOT + nb + qc * 8);
        }
        cpcommit();

        cpwait<1>();          // X (c==0) and C_c complete; W_c may be pending
        __syncthreads();

        // ---- GEMM1 (fp16): S = X @ C^T ----
        float S[2][4][4];
        #pragma unroll
        for (int mt = 0; mt < 2; ++mt)
            #pragma unroll
            for (int nt = 0; nt < 4; ++nt)
                #pragma unroll
                for (int r = 0; r < 4; ++r) S[mt][nt][r] = 0.f;

        #pragma unroll
        for (int kw = 0; kw < 64; kw += 8) {   // word index over k (16 halves/step)
            uint32_t a[2][4], b[4][2];
            #pragma unroll
            for (int mt = 0; mt < 2; ++mt) {
                int r = RM + mt * 16 + gid;
                a[mt][0] = su[XH_O + r * 68 + kw + ctg];
                a[mt][1] = su[XH_O + (r + 8) * 68 + kw + ctg];
                a[mt][2] = su[XH_O + r * 68 + kw + ctg + 4];
                a[mt][3] = su[XH_O + (r + 8) * 68 + kw + ctg + 4];
            }
            #pragma unroll
            for (int nt = 0; nt < 4; ++nt) {
                int n = CN + nt * 8 + gid;
                b[nt][0] = su[CH_O + n * 68 + kw + ctg];
                b[nt][1] = su[CH_O + n * 68 + kw + ctg + 4];
            }
            #pragma unroll
            for (int mt = 0; mt < 2; ++mt)
                #pragma unroll
                for (int nt = 0; nt < 4; ++nt)
                    mma_f16(S[mt][nt], a[mt], b[nt]);
        }

        __syncthreads();      // all warps finished reading C_c

        // ---- prefetch C_{c+1} + c2 into freed buffer ----
        if (c + 1 < CHUNKS) {
            const int nbn = nb + BN;
            #pragma unroll 1
            for (int it = 0; it < 4; ++it) {
                int idx = it * THREADS + tid;
                int row = idx >> 4, qc = idx & 15;
                cp16(sb + (CH_O + row * 68 + qc * 4) * 4,
                     ch_g + (size_t)(nbn + row) * KD + qc * 8);
            }
            if (tid < 16)
                cp16(sb + (C2_O + (par ^ 1) * 64 + tid * 4) * 4, c2_g + nbn + tid * 4);
            cpcommit();
            cpwait<1>();      // W_c complete
        } else {
            cpwait<0>();
        }

        // ---- epilogue: phi = sqrt(1 + max(x2+c2-2S,0)) -> fp16 half2 ----
        #pragma unroll
        for (int mt = 0; mt < 2; ++mt) {
            int rA = RM + mt * 16 + gid, rB = rA + 8;
            float xA = smf[X2_O + rA], xB = smf[X2_O + rB];
            #pragma unroll
            for (int nt = 0; nt < 4; ++nt) {
                int c0 = CN + nt * 8 + 2 * ctg;
                float cc0 = smf[C2_O + par * 64 + c0];
                float cc1 = smf[C2_O + par * 64 + c0 + 1];
                float p0 = fsqrt_ap(1.f + fmaxf(fmaf(-2.f, S[mt][nt][0], xA + cc0), 0.f));
                float p1 = fsqrt_ap(1.f + fmaxf(fmaf(-2.f, S[mt][nt][1], xA + cc1), 0.f));
                float p2 = fsqrt_ap(1.f + fmaxf(fmaf(-2.f, S[mt][nt][2], xB + cc0), 0.f));
                float p3 = fsqrt_ap(1.f + fmaxf(fmaf(-2.f, S[mt][nt][3], xB + cc1), 0.f));
                __half2 hA = __floats2half2_rn(p0, p1);
                __half2 hB = __floats2half2_rn(p2, p3);
                su[PH_O + rA * 36 + (c0 >> 1)] = *(uint32_t*)&hA;
                su[PH_O + rB * 36 + (c0 >> 1)] = *(uint32_t*)&hB;
            }
        }
        __syncthreads();      // phi visible; W_c ready for everyone

        // ---- GEMM2 (fp16): O += phi @ W (k over BN=64 halves) ----
        #pragma unroll
        for (int kw = 0; kw < 32; kw += 8) {   // word index over k (16 halves/step)
            uint32_t ah[2][4], bw[4][2];
            #pragma unroll
            for (int mt = 0; mt < 2; ++mt) {
                int r = RM + mt * 16 + gid;
                ah[mt][0] = su[PH_O + r * 36 + kw + ctg];
                ah[mt][1] = su[PH_O + (r + 8) * 36 + kw + ctg];
                ah[mt][2] = su[PH_O + r * 36 + kw + ctg + 4];
                ah[mt][3] = su[PH_O + (r + 8) * 36 + kw + ctg + 4];
            }
            #pragma unroll
            for (int nt = 0; nt < 4; ++nt) {
                int l = CN + nt * 8 + gid;
                bw[nt][0] = su[WS_O + l * 36 + kw + ctg];
                bw[nt][1] = su[WS_O + l * 36 + kw + ctg + 4];
            }
            #pragma unroll
            for (int mt = 0; mt < 2; ++mt)
                #pragma unroll
                for (int nt = 0; nt < 4; ++nt)
                    mma_f16(O[mt][nt], ah[mt], bw[nt]);
        }
        __syncthreads();      // W_c / phi free for next chunk
    }

    // ---- merge N-splits ----
    #pragma unroll
    for (int mt = 0; mt < 2; ++mt) {
        int rA = db + RM + mt * 16 + gid;
        #pragma unroll
        for (int nt = 0; nt < 4; ++nt) {
            int c0 = CN + nt * 8 + 2 * ctg;
            atomicAdd(&out[(size_t)rA * LD + c0],           O[mt][nt][0]);
            atomicAdd(&out[(size_t)rA * LD + c0 + 1],       O[mt][nt][1]);
            atomicAdd(&out[(size_t)(rA + 8) * LD + c0],     O[mt][nt][2]);
            atomicAdd(&out[(size_t)(rA + 8) * LD + c0 + 1], O[mt][nt][3]);
        }
    }
}

// ---------------------------------------------------------------------------
extern "C" void kernel_launch(void* const* d_in, const int* in_sizes, int n_in,
                              void* d_out, int out_size) {
    const float* xs     = (const float*)d_in[0];
    const float* centre = (const float*)d_in[1];
    const float* weight = (const float*)d_in[2];
    float* out = (float*)d_out;

    cudaFuncSetAttribute(rbfn_main_kernel,
                         cudaFuncAttributeMaxDynamicSharedMemorySize, SMEM_BYTES);

    cudaMemsetAsync(d_out, 0, (size_t)out_size * sizeof(float));
    norms_half_kernel<<<(2 * D_TOT) * 32 / THREADS, THREADS>>>(xs, centre);
    wtrans_kernel<<<(LD * N_TOT) / THREADS, THREADS>>>(weight);
    rbfn_main_kernel<<<64 * NSPLIT, THREADS, SMEM_BYTES>>>(out);
}

// round 6
// speedup vs baseline: 6.8302x; 1.1329x over previous
#include <cuda_runtime.h>
#include <cuda_fp16.h>
#include <cstdint>

// RBFN fused kernel: both GEMMs fp16 mma.sync m16n8k16 (f32 acc), BN=128,
// double-buffered C/W/c2, 2 barriers per iteration.
// out[8192,64] = sqrt(1 + max(x2 + c2 - 2*X@C^T, 0)) @ W

#define D_TOT   8192
#define N_TOT   8192
#define KD      128
#define LD      64
#define BD      128
#define BN      128
#define NSPLIT  2
#define CHUNKS  (N_TOT / BN / NSPLIT)   // 32
#define THREADS 256

// shared memory layout (32-bit word offsets)
#define XH_O 0                    // X tile  [128 rows][68 words] half2 (64 data + 4 pad)
#define CH_O 8704                 // C chunk [2][128][68] half2
#define PH_O 26112                // phi fp16 [128 rows][68 words] (64 data + 4 pad)
#define WS_O 34816                // W^T fp16 [2][64 l][68 words]
#define X2_O 43520                // [128]
#define C2_O 43648                // [2][128]
#define SM_WORDS 43904
#define SMEM_BYTES (SM_WORDS * 4)

#define CH_BUF 8704               // words per C buffer
#define WS_BUF 4352               // words per W buffer

__device__ float  x2_g[D_TOT];
__device__ float  c2_g[N_TOT];
__device__ __half xh_g[D_TOT * KD];    // fp16-rn xs
__device__ __half ch_g[N_TOT * KD];    // fp16-rn centre
__device__ __half wt_g[LD * N_TOT];    // fp16-rn weight, TRANSPOSED [l][n]

// ------------------------- helpers -------------------------
__device__ __forceinline__ uint32_t smem_u32(const void* p) {
    uint32_t a;
    asm("{ .reg .u64 t; cvta.to.shared.u64 t, %1; cvt.u32.u64 %0, t; }" : "=r"(a) : "l"(p));
    return a;
}
__device__ __forceinline__ float fsqrt_ap(float x) {
    float r; asm("sqrt.approx.f32 %0, %1;" : "=f"(r) : "f"(x)); return r;
}
__device__ __forceinline__ void cp16(uint32_t dst, const void* src) {
    asm volatile("cp.async.ca.shared.global [%0], [%1], 16;" :: "r"(dst), "l"(src) : "memory");
}
__device__ __forceinline__ void cpcommit() {
    asm volatile("cp.async.commit_group;" ::: "memory");
}
template <int N>
__device__ __forceinline__ void cpwait() {
    asm volatile("cp.async.wait_group %0;" :: "n"(N) : "memory");
}
__device__ __forceinline__ void mma_f16(float* d, const uint32_t* a, const uint32_t* b) {
    asm volatile("mma.sync.aligned.m16n8k16.row.col.f32.f16.f16.f32 "
                 "{%0,%1,%2,%3}, {%4,%5,%6,%7}, {%8,%9}, {%0,%1,%2,%3};"
                 : "+f"(d[0]), "+f"(d[1]), "+f"(d[2]), "+f"(d[3])
                 : "r"(a[0]), "r"(a[1]), "r"(a[2]), "r"(a[3]),
                   "r"(b[0]), "r"(b[1]));
}

// ---------------------------------------------------------------------------
// Prologue A: row squared norms (exact fp32) + fp16-rn rows of xs/centre.
// ---------------------------------------------------------------------------
__global__ void norms_half_kernel(const float* __restrict__ xs,
                                  const float* __restrict__ centre) {
    int gw   = (blockIdx.x * blockDim.x + threadIdx.x) >> 5;
    int lane = threadIdx.x & 31;
    const float* src; float* dst; __half* dsth; int row;
    if (gw < D_TOT) { src = xs;     dst = x2_g; dsth = xh_g; row = gw; }
    else            { src = centre; dst = c2_g; dsth = ch_g; row = gw - D_TOT; }
    float4 v = ((const float4*)(src + (size_t)row * KD))[lane];

    __half2 h01 = __float22half2_rn(make_float2(v.x, v.y));
    __half2 h23 = __float22half2_rn(make_float2(v.z, v.w));
    uint2 u = make_uint2(*(uint32_t*)&h01, *(uint32_t*)&h23);
    *(uint2*)(dsth + (size_t)row * KD + 4 * lane) = u;

    float s = v.x * v.x + v.y * v.y + v.z * v.z + v.w * v.w;
    #pragma unroll
    for (int off = 16; off; off >>= 1) s += __shfl_xor_sync(0xffffffffu, s, off);
    if (lane == 0) dst[row] = s;
}

// ---------------------------------------------------------------------------
// Prologue B: transpose weight [N][L] -> fp16 [L][N].
// ---------------------------------------------------------------------------
__global__ void wtrans_kernel(const float* __restrict__ weight) {
    int idx = blockIdx.x * blockDim.x + threadIdx.x;   // over LD*N_TOT
    int l = idx >> 13;
    int n = idx & 8191;
    wt_g[(size_t)l * N_TOT + n] = __float2half_rn(weight[(size_t)n * LD + l]);
}

// ---------------------------------------------------------------------------
// chunk-load helpers for the main kernel
// ---------------------------------------------------------------------------
__device__ __forceinline__ void issue_chunk(uint32_t sb, int tid, int buf, int nb) {
    // C chunk: 128 rows x 128 halves = 2048 16B chunks
    #pragma unroll 1
    for (int it = 0; it < 8; ++it) {
        int idx = it * THREADS + tid;
        int row = idx >> 4, qc = idx & 15;
        cp16(sb + (CH_O + buf * CH_BUF + row * 68 + qc * 4) * 4,
             ch_g + (size_t)(nb + row) * KD + qc * 8);
    }
    // W^T chunk: 64 l-rows x 128 halves = 1024 chunks
    #pragma unroll 1
    for (int it = 0; it < 4; ++it) {
        int idx = it * THREADS + tid;
        int l = idx >> 4, qc = idx & 15;
        cp16(sb + (WS_O + buf * WS_BUF + l * 68 + qc * 4) * 4,
             wt_g + (size_t)l * N_TOT + nb + qc * 8);
    }
    // c2: 128 floats = 32 chunks
    if (tid < 32) cp16(sb + (C2_O + buf * 128 + tid * 4) * 4, c2_g + nb + tid * 4);
    cpcommit();
}

// ---------------------------------------------------------------------------
// Main fused kernel. 128 CTAs: d-tile = bid & 63, N-split = bid >> 6.
// GEMM1: wm = wid & 3 (32-row bands), wn1 = wid >> 2 (64-col bands), S[2][8][4].
// GEMM2: same wm, wn2 = wid >> 2 (32-col bands over LD=64), O[2][4][4].
// ---------------------------------------------------------------------------
__global__ __launch_bounds__(THREADS, 1)
void rbfn_main_kernel(float* __restrict__ out) {
    extern __shared__ float smf[];
    uint32_t* su = (uint32_t*)smf;
    const uint32_t sb = smem_u32(smf);

    const int tid = threadIdx.x;
    const int wid = tid >> 5, lid = tid & 31;
    const int gid = lid >> 2, ctg = lid & 3;
    const int wm = wid & 3, wn = wid >> 2;
    const int RM = wm * 32;
    const int CN1 = wn * 64;      // GEMM1 column band (128 cols total)
    const int CN2 = wn * 32;      // GEMM2 column band (64 cols total)

    const int db    = (blockIdx.x & 63) * BD;
    const int split = blockIdx.x >> 6;
    const int nb0   = split * CHUNKS * BN;

    // ---- group 0: X tile + x2 ----
    #pragma unroll 1
    for (int it = 0; it < 8; ++it) {
        int idx = it * THREADS + tid;
        int row = idx >> 4, qc = idx & 15;
        cp16(sb + (XH_O + row * 68 + qc * 4) * 4,
             xh_g + (size_t)(db + row) * KD + qc * 8);
    }
    if (tid < 32) cp16(sb + (X2_O + tid * 4) * 4, x2_g + db + tid * 4);
    cpcommit();

    // ---- group 1: chunk 0 (C, W, c2) ----
    issue_chunk(sb, tid, 0, nb0);

    float O[2][4][4];
    #pragma unroll
    for (int mt = 0; mt < 2; ++mt)
        #pragma unroll
        for (int nt = 0; nt < 4; ++nt)
            #pragma unroll
            for (int r = 0; r < 4; ++r) O[mt][nt][r] = 0.f;

    #pragma unroll 1
    for (int c = 0; c < CHUNKS; ++c) {
        const int par = c & 1;

        // ---- prefetch chunk c+1 into the other buffer, then wait for chunk c ----
        if (c + 1 < CHUNKS) {
            issue_chunk(sb, tid, par ^ 1, nb0 + (c + 1) * BN);
            cpwait<1>();
        } else {
            cpwait<0>();
        }
        __syncthreads();      // chunk c visible; GEMM2(c-1) done -> phi/W-flip safe

        // ---- GEMM1 (fp16): S = X @ C^T, warp tile 32x64 ----
        float S[2][8][4];
        #pragma unroll
        for (int mt = 0; mt < 2; ++mt)
            #pragma unroll
            for (int nt = 0; nt < 8; ++nt)
                #pragma unroll
                for (int r = 0; r < 4; ++r) S[mt][nt][r] = 0.f;

        const uint32_t* __restrict__ chp = su + CH_O + par * CH_BUF;
        #pragma unroll
        for (int kw = 0; kw < 64; kw += 8) {
            uint32_t a[2][4], b[8][2];
            #pragma unroll
            for (int mt = 0; mt < 2; ++mt) {
                int r = RM + mt * 16 + gid;
                a[mt][0] = su[XH_O + r * 68 + kw + ctg];
                a[mt][1] = su[XH_O + (r + 8) * 68 + kw + ctg];
                a[mt][2] = su[XH_O + r * 68 + kw + ctg + 4];
                a[mt][3] = su[XH_O + (r + 8) * 68 + kw + ctg + 4];
            }
            #pragma unroll
            for (int nt = 0; nt < 8; ++nt) {
                int n = CN1 + nt * 8 + gid;
                b[nt][0] = chp[n * 68 + kw + ctg];
                b[nt][1] = chp[n * 68 + kw + ctg + 4];
            }
            #pragma unroll
            for (int mt = 0; mt < 2; ++mt)
                #pragma unroll
                for (int nt = 0; nt < 8; ++nt)
                    mma_f16(S[mt][nt], a[mt], b[nt]);
        }

        // ---- epilogue: phi = sqrt(1 + max(x2+c2-2S,0)) -> fp16 half2 ----
        #pragma unroll
        for (int mt = 0; mt < 2; ++mt) {
            int rA = RM + mt * 16 + gid, rB = rA + 8;
            float xA = smf[X2_O + rA], xB = smf[X2_O + rB];
            #pragma unroll
            for (int nt = 0; nt < 8; ++nt) {
                int c0 = CN1 + nt * 8 + 2 * ctg;
                float cc0 = smf[C2_O + par * 128 + c0];
                float cc1 = smf[C2_O + par * 128 + c0 + 1];
                float p0 = fsqrt_ap(1.f + fmaxf(fmaf(-2.f, S[mt][nt][0], xA + cc0), 0.f));
                float p1 = fsqrt_ap(1.f + fmaxf(fmaf(-2.f, S[mt][nt][1], xA + cc1), 0.f));
                float p2 = fsqrt_ap(1.f + fmaxf(fmaf(-2.f, S[mt][nt][2], xB + cc0), 0.f));
                float p3 = fsqrt_ap(1.f + fmaxf(fmaf(-2.f, S[mt][nt][3], xB + cc1), 0.f));
                __half2 hA = __floats2half2_rn(p0, p1);
                __half2 hB = __floats2half2_rn(p2, p3);
                su[PH_O + rA * 68 + (c0 >> 1)] = *(uint32_t*)&hA;
                su[PH_O + rB * 68 + (c0 >> 1)] = *(uint32_t*)&hB;
            }
        }
        __syncthreads();      // phi visible everywhere; W chunk c resident

        // ---- GEMM2 (fp16): O += phi @ W, k over BN=128 halves ----
        const uint32_t* __restrict__ wsp = su + WS_O + par * WS_BUF;
        #pragma unroll
        for (int kw = 0; kw < 64; kw += 8) {
            uint32_t ah[2][4], bw[4][2];
            #pragma unroll
            for (int mt = 0; mt < 2; ++mt) {
                int r = RM + mt * 16 + gid;
                ah[mt][0] = su[PH_O + r * 68 + kw + ctg];
                ah[mt][1] = su[PH_O + (r + 8) * 68 + kw + ctg];
                ah[mt][2] = su[PH_O + r * 68 + kw + ctg + 4];
                ah[mt][3] = su[PH_O + (r + 8) * 68 + kw + ctg + 4];
            }
            #pragma unroll
            for (int nt = 0; nt < 4; ++nt) {
                int l = CN2 + nt * 8 + gid;
                bw[nt][0] = wsp[l * 68 + kw + ctg];
                bw[nt][1] = wsp[l * 68 + kw + ctg + 4];
            }
            #pragma unroll
            for (int mt = 0; mt < 2; ++mt)
                #pragma unroll
                for (int nt = 0; nt < 4; ++nt)
                    mma_f16(O[mt][nt], ah[mt], bw[nt]);
        }
        // no barrier here: next iteration's first sync covers GEMM2 completion
    }

    // ---- merge N-splits ----
    #pragma unroll
    for (int mt = 0; mt < 2; ++mt) {
        int rA = db + RM + mt * 16 + gid;
        #pragma unroll
        for (int nt = 0; nt < 4; ++nt) {
            int c0 = CN2 + nt * 8 + 2 * ctg;
            atomicAdd(&out[(size_t)rA * LD + c0],           O[mt][nt][0]);
            atomicAdd(&out[(size_t)rA * LD + c0 + 1],       O[mt][nt][1]);
            atomicAdd(&out[(size_t)(rA + 8) * LD + c0],     O[mt][nt][2]);
            atomicAdd(&out[(size_t)(rA + 8) * LD + c0 + 1], O[mt][nt][3]);
        }
    }
}

// ---------------------------------------------------------------------------
extern "C" void kernel_launch(void* const* d_in, const int* in_sizes, int n_in,
                              void* d_out, int out_size) {
    const float* xs     = (const float*)d_in[0];
    const float* centre = (const float*)d_in[1];
    const float* weight = (const float*)d_in[2];
    float* out = (float*)d_out;

    cudaFuncSetAttribute(rbfn_main_kernel,
                         cudaFuncAttributeMaxDynamicSharedMemorySize, SMEM_BYTES);

    cudaMemsetAsync(d_out, 0, (size_t)out_size * sizeof(float));
    norms_half_kernel<<<(2 * D_TOT) * 32 / THREADS, THREADS>>>(xs, centre);
    wtrans_kernel<<<(LD * N_TOT) / THREADS, THREADS>>>(weight);
    rbfn_main_kernel<<<64 * NSPLIT, THREADS, SMEM_BYTES>>>(out);
}